// round 13
// baseline (speedup 1.0000x reference)
#include <cuda_runtime.h>
#include <cuda_bf16.h>
#include <math.h>
#include <stdint.h>

#define Bb 4
#define Cc 256
#define Tt 128
#define NBn 64
#define NFf 512

#define SZ_SMALL (Bb * Cc * Tt * NBn)
#define SZ_BIG   (Bb * Cc * Tt * NFf)
__device__ float g_scratch[(size_t)4 * SZ_SMALL + (size_t)6 * SZ_BIG];

__device__ __forceinline__ uint32_t smem_u32(const void* p) {
    uint32_t a;
    asm("{ .reg .u64 t; cvta.to.shared.u64 t, %1; cvt.u32.u64 %0, t; }" : "=r"(a) : "l"(p));
    return a;
}
#define SWZ128(x) ((x) ^ (((x) >> 3) & 0x70))

__device__ __forceinline__ void split8(float4 a, float4 b, uint32_t* h, uint32_t* l) {
    __nv_bfloat162 h0 = __floats2bfloat162_rn(a.x, a.y);
    __nv_bfloat162 h1 = __floats2bfloat162_rn(a.z, a.w);
    __nv_bfloat162 h2 = __floats2bfloat162_rn(b.x, b.y);
    __nv_bfloat162 h3 = __floats2bfloat162_rn(b.z, b.w);
    float2 f0 = __bfloat1622float2(h0), f1 = __bfloat1622float2(h1);
    float2 f2 = __bfloat1622float2(h2), f3 = __bfloat1622float2(h3);
    __nv_bfloat162 l0 = __floats2bfloat162_rn(a.x - f0.x, a.y - f0.y);
    __nv_bfloat162 l1 = __floats2bfloat162_rn(a.z - f1.x, a.w - f1.y);
    __nv_bfloat162 l2 = __floats2bfloat162_rn(b.x - f2.x, b.y - f2.y);
    __nv_bfloat162 l3 = __floats2bfloat162_rn(b.z - f3.x, b.w - f3.y);
    h[0] = *(uint32_t*)&h0; h[1] = *(uint32_t*)&h1; h[2] = *(uint32_t*)&h2; h[3] = *(uint32_t*)&h3;
    l[0] = *(uint32_t*)&l0; l[1] = *(uint32_t*)&l1; l[2] = *(uint32_t*)&l2; l[3] = *(uint32_t*)&l3;
}

#define LDM_X4(r0, r1, r2, r3, a) \
    asm volatile("ldmatrix.sync.aligned.m8n8.x4.shared.b16 {%0,%1,%2,%3}, [%4];" \
        : "=r"(r0), "=r"(r1), "=r"(r2), "=r"(r3) : "r"(a))
#define MMA_BF16(c, a, b0, b1) \
    asm volatile("mma.sync.aligned.m16n8k16.row.col.f32.bf16.bf16.f32 " \
        "{%0,%1,%2,%3}, {%4,%5,%6,%7}, {%8,%9}, {%0,%1,%2,%3};" \
        : "+f"((c)[0]), "+f"((c)[1]), "+f"((c)[2]), "+f"((c)[3]) \
        : "r"((a)[0]), "r"((a)[1]), "r"((a)[2]), "r"((a)[3]), "r"(b0), "r"(b1))

// ===== HMMA GEMM: Y[b,m,n] = sum_k W[m,k] X[b,k,n], K=256, bf16-split =====
// 256 thr / 8 warps, CTA tile 128m x 128n, warp tile 32m x 64n, Kc=64,
// double-buffered 2x64KB smem, per kk: 12 LDSM -> 48 MMA (density 4.0),
// gload/stage segments interleaved between kk iterations.
__global__ void __launch_bounds__(256) gemm_mma(
    const float* __restrict__ W, const float* __restrict__ X, float* __restrict__ Y,
    const float* __restrict__ bias, const float* __restrict__ skip,
    const float* __restrict__ sscale_p, int Mout, int N, int act) {
    extern __shared__ char smem[];
    const uint32_t sb = smem_u32(smem);
    const int tid = threadIdx.x, wid = tid >> 5, lane = tid & 31;
    const long bXoff = (long)blockIdx.z * 256 * N;
    const long bYoff = (long)blockIdx.z * Mout * N;
    const int n0 = blockIdx.x * 128;
    const int m0 = blockIdx.y * 128;

    const int ag = tid & 3, ar = tid >> 2;   // A staging: k-grp, row base (0..63)

    float aP[32], bP[32];

    auto gloadA = [&](int ch) {
        #pragma unroll
        for (int ir = 0; ir < 2; ir++)
            #pragma unroll
            for (int ig = 0; ig < 2; ig++) {
                const float* s = W + (long)(m0 + ar + ir * 64) * 256 + ch * 64 + (ag + ig * 4) * 8;
                float4 u0 = *(const float4*)s, u1 = *(const float4*)(s + 4);
                int o = (ir * 2 + ig) * 8;
                aP[o+0]=u0.x; aP[o+1]=u0.y; aP[o+2]=u0.z; aP[o+3]=u0.w;
                aP[o+4]=u1.x; aP[o+5]=u1.y; aP[o+6]=u1.z; aP[o+7]=u1.w;
            }
    };
    auto gloadB = [&](int ch) {
        #pragma unroll
        for (int it = 0; it < 4; it++) {
            int n = lane + it * 32;
            const float* s = X + bXoff + (long)(ch * 64 + wid * 8) * N + n0 + n;
            #pragma unroll
            for (int j = 0; j < 8; j++) bP[it*8+j] = s[(long)j * N];
        }
    };
    auto stageA = [&](uint32_t tb) {
        #pragma unroll
        for (int ir = 0; ir < 2; ir++)
            #pragma unroll
            for (int ig = 0; ig < 2; ig++) {
                int o = (ir * 2 + ig) * 8;
                float4 u0 = make_float4(aP[o+0], aP[o+1], aP[o+2], aP[o+3]);
                float4 u1 = make_float4(aP[o+4], aP[o+5], aP[o+6], aP[o+7]);
                uint32_t h[4], l[4];
                split8(u0, u1, h, l);
                uint32_t off = SWZ128((uint32_t)((ar + ir * 64) * 128 + (ag + ig * 4) * 16));
                asm volatile("st.shared.v4.b32 [%0], {%1,%2,%3,%4};" :: "r"(tb + off), "r"(h[0]), "r"(h[1]), "r"(h[2]), "r"(h[3]) : "memory");
                asm volatile("st.shared.v4.b32 [%0], {%1,%2,%3,%4};" :: "r"(tb + 16384 + off), "r"(l[0]), "r"(l[1]), "r"(l[2]), "r"(l[3]) : "memory");
            }
    };
    auto stageB = [&](uint32_t tb) {
        #pragma unroll
        for (int it = 0; it < 4; it++) {
            int n = lane + it * 32;
            float4 u0 = make_float4(bP[it*8+0], bP[it*8+1], bP[it*8+2], bP[it*8+3]);
            float4 u1 = make_float4(bP[it*8+4], bP[it*8+5], bP[it*8+6], bP[it*8+7]);
            uint32_t h[4], l[4];
            split8(u0, u1, h, l);
            uint32_t off = SWZ128((uint32_t)(n * 128 + wid * 16));
            asm volatile("st.shared.v4.b32 [%0], {%1,%2,%3,%4};" :: "r"(tb + 32768 + off), "r"(h[0]), "r"(h[1]), "r"(h[2]), "r"(h[3]) : "memory");
            asm volatile("st.shared.v4.b32 [%0], {%1,%2,%3,%4};" :: "r"(tb + 49152 + off), "r"(l[0]), "r"(l[1]), "r"(l[2]), "r"(l[3]) : "memory");
        }
    };

    const int wm = wid & 3, wn = wid >> 2;   // 4 m-grps x 2 n-grps (warp 32x64)
    float acc[2][8][4];
    #pragma unroll
    for (int mi = 0; mi < 2; mi++)
        #pragma unroll
        for (int ni = 0; ni < 8; ni++)
            #pragma unroll
            for (int r = 0; r < 4; r++) acc[mi][ni][r] = 0.0f;

    uint32_t aRow[2], aMask[2];
    #pragma unroll
    for (int mi = 0; mi < 2; mi++) {
        uint32_t row = wm * 32 + mi * 16 + (lane & 15);
        aRow[mi] = row * 128; aMask[mi] = (aRow[mi] >> 3) & 0x70;
    }
    const uint32_t aKH = (lane >> 4) * 16;
    uint32_t bRow[4], bMask[4];
    #pragma unroll
    for (int pr = 0; pr < 4; pr++) {
        uint32_t nr = wn * 64 + pr * 16 + (lane >> 4) * 8 + (lane & 7);
        bRow[pr] = nr * 128; bMask[pr] = (bRow[pr] >> 3) & 0x70;
    }
    const uint32_t bKH = ((lane >> 3) & 1) * 16;

    // one kk step: 12 LDSM + 48 MMA
    auto kkstep = [&](uint32_t cb, int kk) {
        uint32_t ah[2][4], al[2][4], bh[8][2], bl[8][2];
        const uint32_t ko = (uint32_t)(kk * 32);
        #pragma unroll
        for (int mi = 0; mi < 2; mi++) {
            uint32_t koff = ko + aKH;
            LDM_X4(ah[mi][0], ah[mi][1], ah[mi][2], ah[mi][3],
                   cb + aRow[mi] + (koff ^ aMask[mi]));
            LDM_X4(al[mi][0], al[mi][1], al[mi][2], al[mi][3],
                   cb + 16384 + aRow[mi] + (koff ^ aMask[mi]));
        }
        #pragma unroll
        for (int pr = 0; pr < 4; pr++) {
            uint32_t koff = ko + bKH;
            LDM_X4(bh[pr*2][0], bh[pr*2][1], bh[pr*2+1][0], bh[pr*2+1][1],
                   cb + 32768 + bRow[pr] + (koff ^ bMask[pr]));
            LDM_X4(bl[pr*2][0], bl[pr*2][1], bl[pr*2+1][0], bl[pr*2+1][1],
                   cb + 49152 + bRow[pr] + (koff ^ bMask[pr]));
        }
        #pragma unroll
        for (int mi = 0; mi < 2; mi++)
            #pragma unroll
            for (int ni = 0; ni < 8; ni++)
                MMA_BF16(acc[mi][ni], ah[mi], bh[ni][0], bh[ni][1]);
        #pragma unroll
        for (int mi = 0; mi < 2; mi++)
            #pragma unroll
            for (int ni = 0; ni < 8; ni++)
                MMA_BF16(acc[mi][ni], ah[mi], bl[ni][0], bl[ni][1]);
        #pragma unroll
        for (int mi = 0; mi < 2; mi++)
            #pragma unroll
            for (int ni = 0; ni < 8; ni++)
                MMA_BF16(acc[mi][ni], al[mi], bh[ni][0], bh[ni][1]);
    };

    gloadA(0); gloadB(0);
    stageA(sb); stageB(sb);
    __syncthreads();

    for (int ch = 0; ch < 4; ch++) {
        const uint32_t cb = sb + (uint32_t)(ch & 1) * 65536u;
        const uint32_t nb = sb + (uint32_t)((ch + 1) & 1) * 65536u;
        const bool more = (ch < 3);
        if (more) gloadA(ch + 1);
        kkstep(cb, 0);
        if (more) gloadB(ch + 1);
        kkstep(cb, 1);
        if (more) stageA(nb);
        kkstep(cb, 2);
        kkstep(cb, 3);
        if (more) stageB(nb);
        __syncthreads();
    }

    // epilogue: warp tile 32m x 64n
    const int gid = lane >> 2, tig = lane & 3;
    const float sc = sscale_p ? *sscale_p : 1.0f;
    #pragma unroll
    for (int mi = 0; mi < 2; mi++) {
        #pragma unroll
        for (int ni = 0; ni < 8; ni++) {
            int m1 = m0 + wm * 32 + mi * 16 + gid;
            int n  = n0 + wn * 64 + ni * 8 + tig * 2;
            float v0 = acc[mi][ni][0] + bias[m1];
            float v1 = acc[mi][ni][1] + bias[m1];
            float v2 = acc[mi][ni][2] + bias[m1 + 8];
            float v3 = acc[mi][ni][3] + bias[m1 + 8];
            if (act) {
                v0 = v0 / (1.0f + expf(-v0)); v1 = v1 / (1.0f + expf(-v1));
                v2 = v2 / (1.0f + expf(-v2)); v3 = v3 / (1.0f + expf(-v3));
            }
            long o1 = bYoff + (long)m1 * N + n;
            long o2 = o1 + (long)8 * N;
            if (skip) {
                float2 s1 = *(const float2*)&skip[o1];
                float2 s2 = *(const float2*)&skip[o2];
                v0 += sc * s1.x; v1 += sc * s1.y; v2 += sc * s2.x; v3 += sc * s2.y;
            }
            *(float2*)&Y[o1] = make_float2(v0, v1);
            *(float2*)&Y[o2] = make_float2(v2, v3);
        }
    }
}

// ---------------- RMSNorm (unchanged, passing) ----------------
__global__ void rms_kernel(const float* __restrict__ x, const float* __restrict__ w,
                           float* __restrict__ y, int Wd, int total) {
    int idx = blockIdx.x * blockDim.x + threadIdx.x;
    if (idx >= total) return;
    int wcol = idx % Wd;
    int bt   = idx / Wd;
    int b = bt / Tt, t = bt % Tt;
    long base   = (long)b * Cc * Tt * Wd + (long)t * Wd + wcol;
    long stride = (long)Tt * Wd;
    float sum = 0.0f;
    #pragma unroll 8
    for (int c = 0; c < Cc; c++) {
        float v = x[base + (long)c * stride];
        sum += v * v;
    }
    float sc = rsqrtf(sum * (1.0f / Cc) + 1e-6f);
    #pragma unroll 8
    for (int c = 0; c < Cc; c++)
        y[base + (long)c * stride] = x[base + (long)c * stride] * sc * w[c];
}

// ---------------- SwiGLU (unchanged, passing) ----------------
__global__ void swiglu_kernel(const float* __restrict__ h2, float* __restrict__ u) {
    const int QUARTER = Cc * Tt * NFf / 4;
    long i = (long)blockIdx.x * blockDim.x + threadIdx.x;
    int bq = (int)(i / QUARTER);
    int r  = (int)(i % QUARTER);
    long a_idx = (long)bq * (2 * QUARTER) + r;
    float4 a = ((const float4*)h2)[a_idx];
    float4 g = ((const float4*)h2)[a_idx + QUARTER];
    float4 o;
    o.x = a.x * (g.x / (1.0f + expf(-g.x)));
    o.y = a.y * (g.y / (1.0f + expf(-g.y)));
    o.z = a.z * (g.z / (1.0f + expf(-g.z)));
    o.w = a.w * (g.w / (1.0f + expf(-g.w)));
    ((float4*)u)[i] = o;
}

// ---------------- fused attention (unchanged, passing) ----------------
__global__ void __launch_bounds__(256) attn_kernel(
    const float* __restrict__ q, const float* __restrict__ k, const float* __restrict__ v,
    const float* __restrict__ eb, const float* __restrict__ ssp, const float* __restrict__ psp,
    float* __restrict__ att) {
    __shared__ float sm[64 * 128 + 64 * 36];
    float* wst = sm;
    float* vs  = sm + 64 * 128;
    float* qs  = sm;
    float* ks  = sm + 32 * 128;

    const int f0 = blockIdx.x * 128;
    const int t  = blockIdx.y;
    const int b  = blockIdx.z;
    const int tid = threadIdx.x;
    const long qbase = (long)b * Cc * Tt * NFf + (long)t * NFf;
    const long kbase = (long)b * Cc * Tt * NBn + (long)t * NBn;
    const float ss = *ssp, ps = *psp;
    const int tx = tid & 15, ty = tid >> 4;

    float s[8][4];
    #pragma unroll
    for (int i = 0; i < 8; i++)
        #pragma unroll
        for (int j = 0; j < 4; j++) s[i][j] = 0.0f;

    for (int c0 = 0; c0 < Cc; c0 += 32) {
        {
            const int fc = (tid & 31) << 2;
            const int cr = tid >> 5;
            #pragma unroll
            for (int r = 0; r < 4; r++) {
                int cc = cr + r * 8;
                *(float4*)&qs[cc * 128 + fc] =
                    *(const float4*)&q[qbase + (long)(c0 + cc) * Tt * NFf + f0 + fc];
            }
            const int nc  = (tid & 15) << 2;
            const int cr2 = tid >> 4;
            #pragma unroll
            for (int r = 0; r < 2; r++) {
                int cc = cr2 + r * 16;
                *(float4*)&ks[cc * 64 + nc] =
                    *(const float4*)&k[kbase + (long)(c0 + cc) * Tt * NBn + nc];
            }
        }
        __syncthreads();
        #pragma unroll 8
        for (int cc = 0; cc < 32; cc++) {
            float4 a0 = *(float4*)&qs[cc * 128 + ty * 8];
            float4 a1 = *(float4*)&qs[cc * 128 + ty * 8 + 4];
            float4 b4 = *(float4*)&ks[cc * 64 + tx * 4];
            float av[8] = {a0.x, a0.y, a0.z, a0.w, a1.x, a1.y, a1.z, a1.w};
            float bv[4] = {b4.x, b4.y, b4.z, b4.w};
            #pragma unroll
            for (int i = 0; i < 8; i++)
                #pragma unroll
                for (int j = 0; j < 4; j++)
                    s[i][j] += av[i] * bv[j];
        }
        __syncthreads();
    }

    #pragma unroll
    for (int i = 0; i < 8; i++) {
        const int f = f0 + ty * 8 + i;
        float mx = -1e30f;
        #pragma unroll
        for (int j = 0; j < 4; j++) {
            s[i][j] = s[i][j] * ss + eb[(tx * 4 + j) * NFf + f] * ps;
            mx = fmaxf(mx, s[i][j]);
        }
        #pragma unroll
        for (int o = 8; o > 0; o >>= 1)
            mx = fmaxf(mx, __shfl_xor_sync(0xffffffffu, mx, o, 16));
        float sum = 0.0f;
        #pragma unroll
        for (int j = 0; j < 4; j++) { float e = expf(s[i][j] - mx); s[i][j] = e; sum += e; }
        #pragma unroll
        for (int o = 8; o > 0; o >>= 1)
            sum += __shfl_xor_sync(0xffffffffu, sum, o, 16);
        float inv = 1.0f / sum;
        #pragma unroll
        for (int j = 0; j < 4; j++) s[i][j] *= inv;
    }

    #pragma unroll
    for (int i = 0; i < 8; i++)
        #pragma unroll
        for (int j = 0; j < 4; j++)
            wst[(tx * 4 + j) * 128 + ty * 8 + i] = s[i][j];

    const int fx = tid & 15, cg = tid >> 4;
    for (int c0 = 0; c0 < Cc; c0 += 32) {
        {
            const int nc = (tid & 15) << 2;
            const int cr = tid >> 4;
            #pragma unroll
            for (int r = 0; r < 2; r++) {
                int cc = cr + r * 16;
                float4 vv4 = *(const float4*)&v[kbase + (long)(c0 + cc) * Tt * NBn + nc];
                vs[(nc + 0) * 36 + cc] = vv4.x;
                vs[(nc + 1) * 36 + cc] = vv4.y;
                vs[(nc + 2) * 36 + cc] = vv4.z;
                vs[(nc + 3) * 36 + cc] = vv4.w;
            }
        }
        __syncthreads();
        float a0[8], a1[8];
        #pragma unroll
        for (int jj = 0; jj < 8; jj++) { a0[jj] = 0.0f; a1[jj] = 0.0f; }
        #pragma unroll 16
        for (int n = 0; n < 64; n++) {
            float4 wa = *(float4*)&wst[n * 128 + fx * 8];
            float4 wb = *(float4*)&wst[n * 128 + fx * 8 + 4];
            float2 vv = *(float2*)&vs[n * 36 + cg * 2];
            float w8[8] = {wa.x, wa.y, wa.z, wa.w, wb.x, wb.y, wb.z, wb.w};
            #pragma unroll
            for (int jj = 0; jj < 8; jj++) {
                a0[jj] += vv.x * w8[jj];
                a1[jj] += vv.y * w8[jj];
            }
        }
        int c = c0 + cg * 2;
        long o0 = qbase + (long)c * Tt * NFf + f0 + fx * 8;
        long o1 = o0 + (long)Tt * NFf;
        *(float4*)&att[o0]     = make_float4(a0[0], a0[1], a0[2], a0[3]);
        *(float4*)&att[o0 + 4] = make_float4(a0[4], a0[5], a0[6], a0[7]);
        *(float4*)&att[o1]     = make_float4(a1[0], a1[1], a1[2], a1[3]);
        *(float4*)&att[o1 + 4] = make_float4(a1[4], a1[5], a1[6], a1[7]);
        __syncthreads();
    }
}

// ---------------- launch ----------------
#define GEMM_SMEM 131072
extern "C" void kernel_launch(void* const* d_in, const int* in_sizes, int n_in,
                              void* d_out, int out_size) {
    (void)in_sizes; (void)n_in; (void)out_size;
    const float* latent = (const float*)d_in[0];
    const float* side   = (const float*)d_in[1];
    const float* eb     = (const float*)d_in[2];
    const float* lp_nw  = (const float*)d_in[3];
    const float* lp_w   = (const float*)d_in[4];
    const float* lp_b   = (const float*)d_in[5];
    const float* qn_w   = (const float*)d_in[6];
    const float* qin_w  = (const float*)d_in[7];
    const float* qin_b  = (const float*)d_in[8];
    const float* qout_w = (const float*)d_in[9];
    const float* qout_b = (const float*)d_in[10];
    const float* q_w    = (const float*)d_in[11];
    const float* q_b    = (const float*)d_in[12];
    const float* k_w    = (const float*)d_in[13];
    const float* k_b    = (const float*)d_in[14];
    const float* v_w    = (const float*)d_in[15];
    const float* v_b    = (const float*)d_in[16];
    const float* o_w    = (const float*)d_in[17];
    const float* o_b    = (const float*)d_in[18];
    const float* ffn_nw = (const float*)d_in[19];
    const float* fin_w  = (const float*)d_in[20];
    const float* fin_b  = (const float*)d_in[21];
    const float* fout_w = (const float*)d_in[22];
    const float* fout_b = (const float*)d_in[23];
    const float* ss     = (const float*)d_in[24];
    const float* ps     = (const float*)d_in[25];
    const float* qss    = (const float*)d_in[26];
    float* out = (float*)d_out;

    float* base = nullptr;
    cudaGetSymbolAddress((void**)&base, g_scratch);
    float* p_ln  = base;
    float* p_lh  = base + (size_t)1 * SZ_SMALL;
    float* p_k   = base + (size_t)2 * SZ_SMALL;
    float* p_v   = base + (size_t)3 * SZ_SMALL;
    float* p_A   = base + (size_t)4 * SZ_SMALL;
    float* p_h2  = p_A  + (size_t)1 * SZ_BIG;
    float* p_u   = p_h2 + (size_t)2 * SZ_BIG;
    float* p_qh  = p_u  + (size_t)1 * SZ_BIG;
    float* p_hid = p_qh + (size_t)1 * SZ_BIG;

    cudaFuncSetAttribute(gemm_mma, cudaFuncAttributeMaxDynamicSharedMemorySize, GEMM_SMEM);

    const int NTB = Tt * NBn;   // 8192
    const int NTF = Tt * NFf;   // 65536

    // latent path
    rms_kernel<<<(Bb * Tt * NBn) / 256, 256>>>(latent, lp_nw, p_ln, NBn, Bb * Tt * NBn);
    dim3 gNB(NTB / 128, 2, Bb);
    gemm_mma<<<gNB, 256, GEMM_SMEM>>>(lp_w, p_ln, p_lh, lp_b, nullptr, nullptr, Cc, NTB, 1);
    gemm_mma<<<gNB, 256, GEMM_SMEM>>>(k_w, p_lh, p_k, k_b, nullptr, nullptr, Cc, NTB, 0);
    gemm_mma<<<gNB, 256, GEMM_SMEM>>>(v_w, p_lh, p_v, v_b, nullptr, nullptr, Cc, NTB, 0);

    // query path
    rms_kernel<<<(Bb * Tt * NFf) / 256, 256>>>(side, qn_w, p_A, NFf, Bb * Tt * NFf);
    dim3 gIN(NTF / 128, 4, Bb);
    gemm_mma<<<gIN, 256, GEMM_SMEM>>>(qin_w, p_A, p_h2, qin_b, nullptr, nullptr, 2 * Cc, NTF, 0);
    swiglu_kernel<<<(Bb * Cc * Tt * NFf / 4) / 256, 256>>>(p_h2, p_u);
    dim3 gNF(NTF / 128, 2, Bb);
    gemm_mma<<<gNF, 256, GEMM_SMEM>>>(qout_w, p_u, p_qh, qout_b, nullptr, nullptr, Cc, NTF, 0);
    gemm_mma<<<gNF, 256, GEMM_SMEM>>>(q_w, p_qh, p_A, q_b, nullptr, nullptr, Cc, NTF, 0);

    // attention
    attn_kernel<<<dim3(NFf / 128, Tt, Bb), 256>>>(p_A, p_k, p_v, eb, ss, ps, p_u);

    // output proj + query skip
    gemm_mma<<<gNF, 256, GEMM_SMEM>>>(o_w, p_u, p_hid, o_b, p_qh, qss, Cc, NTF, 0);

    // FFN
    rms_kernel<<<(Bb * Tt * NFf) / 256, 256>>>(p_hid, ffn_nw, p_A, NFf, Bb * Tt * NFf);
    gemm_mma<<<gIN, 256, GEMM_SMEM>>>(fin_w, p_A, p_h2, fin_b, nullptr, nullptr, 2 * Cc, NTF, 0);
    swiglu_kernel<<<(Bb * Cc * Tt * NFf / 4) / 256, 256>>>(p_h2, p_u);
    gemm_mma<<<gNF, 256, GEMM_SMEM>>>(fout_w, p_u, out, fout_b, p_hid, nullptr, Cc, NTF, 0);
}

// round 14
// speedup vs baseline: 1.0539x; 1.0539x over previous
#include <cuda_runtime.h>
#include <cuda_bf16.h>
#include <math.h>
#include <stdint.h>

#define Bb 4
#define Cc 256
#define Tt 128
#define NBn 64
#define NFf 512

#define SZ_SMALL (Bb * Cc * Tt * NBn)
#define SZ_BIG   (Bb * Cc * Tt * NFf)
#define SZ_WPACK (1 << 20)
__device__ float g_scratch[(size_t)4 * SZ_SMALL + (size_t)6 * SZ_BIG + SZ_WPACK];

__device__ __forceinline__ uint32_t smem_u32(const void* p) {
    uint32_t a;
    asm("{ .reg .u64 t; cvta.to.shared.u64 t, %1; cvt.u32.u64 %0, t; }" : "=r"(a) : "l"(p));
    return a;
}
#define SWZ128(x) ((x) ^ (((x) >> 3) & 0x70))

// pack fp32 -> (hi bf16 << 16) | lo bf16
__device__ __forceinline__ uint32_t packf(float x) {
    __nv_bfloat16 h = __float2bfloat16(x);
    float hf = __bfloat162float(h);
    __nv_bfloat16 l = __float2bfloat16(x - hf);
    return ((uint32_t)__bfloat16_as_ushort(h) << 16) | (uint32_t)__bfloat16_as_ushort(l);
}
__device__ __forceinline__ float unpackf(uint32_t u) {
    return __bfloat162float(__ushort_as_bfloat16((unsigned short)(u >> 16))) +
           __bfloat162float(__ushort_as_bfloat16((unsigned short)(u & 0xFFFFu)));
}

#define LDM_X4(r0, r1, r2, r3, a) \
    asm volatile("ldmatrix.sync.aligned.m8n8.x4.shared.b16 {%0,%1,%2,%3}, [%4];" \
        : "=r"(r0), "=r"(r1), "=r"(r2), "=r"(r3) : "r"(a))
#define MMA_BF16(c, a, b0, b1) \
    asm volatile("mma.sync.aligned.m16n8k16.row.col.f32.bf16.bf16.f32 " \
        "{%0,%1,%2,%3}, {%4,%5,%6,%7}, {%8,%9}, {%0,%1,%2,%3};" \
        : "+f"((c)[0]), "+f"((c)[1]), "+f"((c)[2]), "+f"((c)[3]) \
        : "r"((a)[0]), "r"((a)[1]), "r"((a)[2]), "r"((a)[3]), "r"(b0), "r"(b1))

// ---- weight pack kernel ----
__global__ void packw_kernel(const float* __restrict__ in, uint32_t* __restrict__ out, int n) {
    int i = blockIdx.x * blockDim.x + threadIdx.x;
    if (i < n) out[i] = packf(in[i]);
}

// ===== HMMA GEMM on pre-split packed operands =====
// Y[b,m,n] = sum_k W[m,k] X[b,k,n], K=256; W,X packed u32 (hi|lo bf16).
// 512 thr / 16 warps, tile 128x128, Kc=64, double-buffered 2x64KB smem,
// per kk: 8 LDSM -> 24 MMA. Staging = load packed + PRMT + STS (no cvt math).
__global__ void __launch_bounds__(512) gemm_mma(
    const uint32_t* __restrict__ W, const uint32_t* __restrict__ X, void* __restrict__ Yv,
    const float* __restrict__ bias, const float* __restrict__ skipF,
    const uint32_t* __restrict__ skipP, const float* __restrict__ sscale_p,
    int Mout, int N, int act, int outMode) {
    extern __shared__ char smem[];
    const uint32_t sb = smem_u32(smem);
    const int tid = threadIdx.x, wid = tid >> 5, lane = tid & 31;
    const long bXoff = (long)blockIdx.z * 256 * N;
    const long bYoff = (long)blockIdx.z * Mout * N;
    const int n0 = blockIdx.x * 128;
    const int m0 = blockIdx.y * 128;

    const int ag = tid & 7, ar = tid >> 3;          // A staging: k-grp, row
    const int bkg = wid & 7, bnh = wid >> 3;        // B staging: k-grp, n-half

    uint32_t aP[16], bP[16];

    auto stage = [&](uint32_t tb) {
        #pragma unroll
        for (int it = 0; it < 2; it++) {
            const uint32_t* p = &aP[it * 8];
            uint32_t h0 = __byte_perm(p[0], p[1], 0x7632), l0 = __byte_perm(p[0], p[1], 0x5410);
            uint32_t h1 = __byte_perm(p[2], p[3], 0x7632), l1 = __byte_perm(p[2], p[3], 0x5410);
            uint32_t h2 = __byte_perm(p[4], p[5], 0x7632), l2 = __byte_perm(p[4], p[5], 0x5410);
            uint32_t h3 = __byte_perm(p[6], p[7], 0x7632), l3 = __byte_perm(p[6], p[7], 0x5410);
            uint32_t off = SWZ128((uint32_t)((ar + it * 64) * 128 + ag * 16));
            asm volatile("st.shared.v4.b32 [%0], {%1,%2,%3,%4};" :: "r"(tb + off), "r"(h0), "r"(h1), "r"(h2), "r"(h3) : "memory");
            asm volatile("st.shared.v4.b32 [%0], {%1,%2,%3,%4};" :: "r"(tb + 16384 + off), "r"(l0), "r"(l1), "r"(l2), "r"(l3) : "memory");
        }
        #pragma unroll
        for (int it = 0; it < 2; it++) {
            int n = lane + bnh * 32 + it * 64;
            const uint32_t* p = &bP[it * 8];
            uint32_t h0 = __byte_perm(p[0], p[1], 0x7632), l0 = __byte_perm(p[0], p[1], 0x5410);
            uint32_t h1 = __byte_perm(p[2], p[3], 0x7632), l1 = __byte_perm(p[2], p[3], 0x5410);
            uint32_t h2 = __byte_perm(p[4], p[5], 0x7632), l2 = __byte_perm(p[4], p[5], 0x5410);
            uint32_t h3 = __byte_perm(p[6], p[7], 0x7632), l3 = __byte_perm(p[6], p[7], 0x5410);
            uint32_t off = SWZ128((uint32_t)(n * 128 + bkg * 16));
            asm volatile("st.shared.v4.b32 [%0], {%1,%2,%3,%4};" :: "r"(tb + 32768 + off), "r"(h0), "r"(h1), "r"(h2), "r"(h3) : "memory");
            asm volatile("st.shared.v4.b32 [%0], {%1,%2,%3,%4};" :: "r"(tb + 49152 + off), "r"(l0), "r"(l1), "r"(l2), "r"(l3) : "memory");
        }
    };
    auto gload = [&](int ch) {
        #pragma unroll
        for (int it = 0; it < 2; it++) {
            const uint32_t* s = W + (long)(m0 + ar + it * 64) * 256 + ch * 64 + ag * 8;
            uint4 u0 = *(const uint4*)s, u1 = *(const uint4*)(s + 4);
            aP[it*8+0]=u0.x; aP[it*8+1]=u0.y; aP[it*8+2]=u0.z; aP[it*8+3]=u0.w;
            aP[it*8+4]=u1.x; aP[it*8+5]=u1.y; aP[it*8+6]=u1.z; aP[it*8+7]=u1.w;
        }
        #pragma unroll
        for (int it = 0; it < 2; it++) {
            int n = lane + bnh * 32 + it * 64;
            const uint32_t* s = X + bXoff + (long)(ch * 64 + bkg * 8) * N + n0 + n;
            #pragma unroll
            for (int j = 0; j < 8; j++) bP[it*8+j] = s[(long)j * N];
        }
    };

    const int wm = wid & 3, wn = wid >> 2;
    float acc[2][4][4];
    #pragma unroll
    for (int mi = 0; mi < 2; mi++)
        #pragma unroll
        for (int ni = 0; ni < 4; ni++)
            #pragma unroll
            for (int r = 0; r < 4; r++) acc[mi][ni][r] = 0.0f;

    uint32_t aRow[2], aMask[2];
    #pragma unroll
    for (int mi = 0; mi < 2; mi++) {
        uint32_t row = wm * 32 + mi * 16 + (lane & 15);
        aRow[mi] = row * 128; aMask[mi] = (aRow[mi] >> 3) & 0x70;
    }
    const uint32_t aKH = (lane >> 4) * 16;
    uint32_t bRow[2], bMask[2];
    #pragma unroll
    for (int pr = 0; pr < 2; pr++) {
        uint32_t nr = wn * 32 + pr * 16 + (lane >> 4) * 8 + (lane & 7);
        bRow[pr] = nr * 128; bMask[pr] = (bRow[pr] >> 3) & 0x70;
    }
    const uint32_t bKH = ((lane >> 3) & 1) * 16;

    gload(0);
    stage(sb);
    __syncthreads();

    for (int ch = 0; ch < 4; ch++) {
        if (ch < 3) gload(ch + 1);
        const uint32_t cb = sb + (uint32_t)(ch & 1) * 65536u;
        #pragma unroll
        for (int kk = 0; kk < 4; kk++) {
            uint32_t ah[2][4], al[2][4], bh[4][2], bl[4][2];
            const uint32_t ko = (uint32_t)(kk * 32);
            #pragma unroll
            for (int mi = 0; mi < 2; mi++) {
                uint32_t koff = ko + aKH;
                LDM_X4(ah[mi][0], ah[mi][1], ah[mi][2], ah[mi][3],
                       cb + aRow[mi] + (koff ^ aMask[mi]));
                LDM_X4(al[mi][0], al[mi][1], al[mi][2], al[mi][3],
                       cb + 16384 + aRow[mi] + (koff ^ aMask[mi]));
            }
            #pragma unroll
            for (int pr = 0; pr < 2; pr++) {
                uint32_t koff = ko + bKH;
                LDM_X4(bh[pr*2][0], bh[pr*2][1], bh[pr*2+1][0], bh[pr*2+1][1],
                       cb + 32768 + bRow[pr] + (koff ^ bMask[pr]));
                LDM_X4(bl[pr*2][0], bl[pr*2][1], bl[pr*2+1][0], bl[pr*2+1][1],
                       cb + 49152 + bRow[pr] + (koff ^ bMask[pr]));
            }
            #pragma unroll
            for (int mi = 0; mi < 2; mi++)
                #pragma unroll
                for (int ni = 0; ni < 4; ni++)
                    MMA_BF16(acc[mi][ni], ah[mi], bh[ni][0], bh[ni][1]);
            #pragma unroll
            for (int mi = 0; mi < 2; mi++)
                #pragma unroll
                for (int ni = 0; ni < 4; ni++)
                    MMA_BF16(acc[mi][ni], ah[mi], bl[ni][0], bl[ni][1]);
            #pragma unroll
            for (int mi = 0; mi < 2; mi++)
                #pragma unroll
                for (int ni = 0; ni < 4; ni++)
                    MMA_BF16(acc[mi][ni], al[mi], bh[ni][0], bh[ni][1]);
        }
        if (ch < 3) stage(sb + (uint32_t)((ch + 1) & 1) * 65536u);
        __syncthreads();
    }

    // epilogue
    const int gid = lane >> 2, tig = lane & 3;
    const float sc = sscale_p ? *sscale_p : 1.0f;
    float* Yf = (float*)Yv;
    uint32_t* Yp = (uint32_t*)Yv;
    #pragma unroll
    for (int mi = 0; mi < 2; mi++) {
        #pragma unroll
        for (int ni = 0; ni < 4; ni++) {
            int m1 = m0 + wm * 32 + mi * 16 + gid;
            int n  = n0 + wn * 32 + ni * 8 + tig * 2;
            float v0 = acc[mi][ni][0] + bias[m1];
            float v1 = acc[mi][ni][1] + bias[m1];
            float v2 = acc[mi][ni][2] + bias[m1 + 8];
            float v3 = acc[mi][ni][3] + bias[m1 + 8];
            if (act) {
                v0 = v0 / (1.0f + expf(-v0)); v1 = v1 / (1.0f + expf(-v1));
                v2 = v2 / (1.0f + expf(-v2)); v3 = v3 / (1.0f + expf(-v3));
            }
            long o1 = bYoff + (long)m1 * N + n;
            long o2 = o1 + (long)8 * N;
            if (skipF) {
                float2 s1 = *(const float2*)&skipF[o1];
                float2 s2 = *(const float2*)&skipF[o2];
                v0 += sc * s1.x; v1 += sc * s1.y; v2 += sc * s2.x; v3 += sc * s2.y;
            } else if (skipP) {
                uint2 s1 = *(const uint2*)&skipP[o1];
                uint2 s2 = *(const uint2*)&skipP[o2];
                v0 += sc * unpackf(s1.x); v1 += sc * unpackf(s1.y);
                v2 += sc * unpackf(s2.x); v3 += sc * unpackf(s2.y);
            }
            if (outMode == 0) {
                *(float2*)&Yf[o1] = make_float2(v0, v1);
                *(float2*)&Yf[o2] = make_float2(v2, v3);
            } else {
                *(uint2*)&Yp[o1] = make_uint2(packf(v0), packf(v1));
                *(uint2*)&Yp[o2] = make_uint2(packf(v2), packf(v3));
            }
        }
    }
}

// ---------------- RMSNorm: fp32 in -> packed out (consumers are GEMMs) -------
__global__ void rms_kernel(const float* __restrict__ x, const float* __restrict__ w,
                           uint32_t* __restrict__ y, int Wd, int total) {
    int idx = blockIdx.x * blockDim.x + threadIdx.x;
    if (idx >= total) return;
    int wcol = idx % Wd;
    int bt   = idx / Wd;
    int b = bt / Tt, t = bt % Tt;
    long base   = (long)b * Cc * Tt * Wd + (long)t * Wd + wcol;
    long stride = (long)Tt * Wd;
    float sum = 0.0f;
    #pragma unroll 8
    for (int c = 0; c < Cc; c++) {
        float v = x[base + (long)c * stride];
        sum += v * v;
    }
    float sc = rsqrtf(sum * (1.0f / Cc) + 1e-6f);
    #pragma unroll 8
    for (int c = 0; c < Cc; c++)
        y[base + (long)c * stride] = packf(x[base + (long)c * stride] * sc * w[c]);
}

// ---------------- SwiGLU: fp32 h2 -> packed u -------------------------------
__global__ void swiglu_kernel(const float* __restrict__ h2, uint32_t* __restrict__ u) {
    const int QUARTER = Cc * Tt * NFf / 4;
    long i = (long)blockIdx.x * blockDim.x + threadIdx.x;
    int bq = (int)(i / QUARTER);
    int r  = (int)(i % QUARTER);
    long a_idx = (long)bq * (2 * QUARTER) + r;
    float4 a = ((const float4*)h2)[a_idx];
    float4 g = ((const float4*)h2)[a_idx + QUARTER];
    uint4 o;
    o.x = packf(a.x * (g.x / (1.0f + expf(-g.x))));
    o.y = packf(a.y * (g.y / (1.0f + expf(-g.y))));
    o.z = packf(a.z * (g.z / (1.0f + expf(-g.z))));
    o.w = packf(a.w * (g.w / (1.0f + expf(-g.w))));
    ((uint4*)u)[i] = o;
}

// ---------------- fused attention: fp32 q/k/v in, packed att out -------------
__global__ void __launch_bounds__(256) attn_kernel(
    const float* __restrict__ q, const float* __restrict__ k, const float* __restrict__ v,
    const float* __restrict__ eb, const float* __restrict__ ssp, const float* __restrict__ psp,
    uint32_t* __restrict__ att) {
    __shared__ float sm[64 * 128 + 64 * 36];
    float* wst = sm;
    float* vs  = sm + 64 * 128;
    float* qs  = sm;
    float* ks  = sm + 32 * 128;

    const int f0 = blockIdx.x * 128;
    const int t  = blockIdx.y;
    const int b  = blockIdx.z;
    const int tid = threadIdx.x;
    const long qbase = (long)b * Cc * Tt * NFf + (long)t * NFf;
    const long kbase = (long)b * Cc * Tt * NBn + (long)t * NBn;
    const float ss = *ssp, ps = *psp;
    const int tx = tid & 15, ty = tid >> 4;

    float s[8][4];
    #pragma unroll
    for (int i = 0; i < 8; i++)
        #pragma unroll
        for (int j = 0; j < 4; j++) s[i][j] = 0.0f;

    for (int c0 = 0; c0 < Cc; c0 += 32) {
        {
            const int fc = (tid & 31) << 2;
            const int cr = tid >> 5;
            #pragma unroll
            for (int r = 0; r < 4; r++) {
                int cc = cr + r * 8;
                *(float4*)&qs[cc * 128 + fc] =
                    *(const float4*)&q[qbase + (long)(c0 + cc) * Tt * NFf + f0 + fc];
            }
            const int nc  = (tid & 15) << 2;
            const int cr2 = tid >> 4;
            #pragma unroll
            for (int r = 0; r < 2; r++) {
                int cc = cr2 + r * 16;
                *(float4*)&ks[cc * 64 + nc] =
                    *(const float4*)&k[kbase + (long)(c0 + cc) * Tt * NBn + nc];
            }
        }
        __syncthreads();
        #pragma unroll 8
        for (int cc = 0; cc < 32; cc++) {
            float4 a0 = *(float4*)&qs[cc * 128 + ty * 8];
            float4 a1 = *(float4*)&qs[cc * 128 + ty * 8 + 4];
            float4 b4 = *(float4*)&ks[cc * 64 + tx * 4];
            float av[8] = {a0.x, a0.y, a0.z, a0.w, a1.x, a1.y, a1.z, a1.w};
            float bv[4] = {b4.x, b4.y, b4.z, b4.w};
            #pragma unroll
            for (int i = 0; i < 8; i++)
                #pragma unroll
                for (int j = 0; j < 4; j++)
                    s[i][j] += av[i] * bv[j];
        }
        __syncthreads();
    }

    #pragma unroll
    for (int i = 0; i < 8; i++) {
        const int f = f0 + ty * 8 + i;
        float mx = -1e30f;
        #pragma unroll
        for (int j = 0; j < 4; j++) {
            s[i][j] = s[i][j] * ss + eb[(tx * 4 + j) * NFf + f] * ps;
            mx = fmaxf(mx, s[i][j]);
        }
        #pragma unroll
        for (int o = 8; o > 0; o >>= 1)
            mx = fmaxf(mx, __shfl_xor_sync(0xffffffffu, mx, o, 16));
        float sum = 0.0f;
        #pragma unroll
        for (int j = 0; j < 4; j++) { float e = expf(s[i][j] - mx); s[i][j] = e; sum += e; }
        #pragma unroll
        for (int o = 8; o > 0; o >>= 1)
            sum += __shfl_xor_sync(0xffffffffu, sum, o, 16);
        float inv = 1.0f / sum;
        #pragma unroll
        for (int j = 0; j < 4; j++) s[i][j] *= inv;
    }

    #pragma unroll
    for (int i = 0; i < 8; i++)
        #pragma unroll
        for (int j = 0; j < 4; j++)
            wst[(tx * 4 + j) * 128 + ty * 8 + i] = s[i][j];

    const int fx = tid & 15, cg = tid >> 4;
    for (int c0 = 0; c0 < Cc; c0 += 32) {
        {
            const int nc = (tid & 15) << 2;
            const int cr = tid >> 4;
            #pragma unroll
            for (int r = 0; r < 2; r++) {
                int cc = cr + r * 16;
                float4 vv4 = *(const float4*)&v[kbase + (long)(c0 + cc) * Tt * NBn + nc];
                vs[(nc + 0) * 36 + cc] = vv4.x;
                vs[(nc + 1) * 36 + cc] = vv4.y;
                vs[(nc + 2) * 36 + cc] = vv4.z;
                vs[(nc + 3) * 36 + cc] = vv4.w;
            }
        }
        __syncthreads();
        float a0[8], a1[8];
        #pragma unroll
        for (int jj = 0; jj < 8; jj++) { a0[jj] = 0.0f; a1[jj] = 0.0f; }
        #pragma unroll 16
        for (int n = 0; n < 64; n++) {
            float4 wa = *(float4*)&wst[n * 128 + fx * 8];
            float4 wb = *(float4*)&wst[n * 128 + fx * 8 + 4];
            float2 vv = *(float2*)&vs[n * 36 + cg * 2];
            float w8[8] = {wa.x, wa.y, wa.z, wa.w, wb.x, wb.y, wb.z, wb.w};
            #pragma unroll
            for (int jj = 0; jj < 8; jj++) {
                a0[jj] += vv.x * w8[jj];
                a1[jj] += vv.y * w8[jj];
            }
        }
        int c = c0 + cg * 2;
        long o0 = qbase + (long)c * Tt * NFf + f0 + fx * 8;
        long o1 = o0 + (long)Tt * NFf;
        *(uint4*)&att[o0]     = make_uint4(packf(a0[0]), packf(a0[1]), packf(a0[2]), packf(a0[3]));
        *(uint4*)&att[o0 + 4] = make_uint4(packf(a0[4]), packf(a0[5]), packf(a0[6]), packf(a0[7]));
        *(uint4*)&att[o1]     = make_uint4(packf(a1[0]), packf(a1[1]), packf(a1[2]), packf(a1[3]));
        *(uint4*)&att[o1 + 4] = make_uint4(packf(a1[4]), packf(a1[5]), packf(a1[6]), packf(a1[7]));
        __syncthreads();
    }
}

// ---------------- launch ----------------
#define GEMM_SMEM 131072
extern "C" void kernel_launch(void* const* d_in, const int* in_sizes, int n_in,
                              void* d_out, int out_size) {
    (void)in_sizes; (void)n_in; (void)out_size;
    const float* latent = (const float*)d_in[0];
    const float* side   = (const float*)d_in[1];
    const float* eb     = (const float*)d_in[2];
    const float* lp_nw  = (const float*)d_in[3];
    const float* lp_w   = (const float*)d_in[4];
    const float* lp_b   = (const float*)d_in[5];
    const float* qn_w   = (const float*)d_in[6];
    const float* qin_w  = (const float*)d_in[7];
    const float* qin_b  = (const float*)d_in[8];
    const float* qout_w = (const float*)d_in[9];
    const float* qout_b = (const float*)d_in[10];
    const float* q_w    = (const float*)d_in[11];
    const float* q_b    = (const float*)d_in[12];
    const float* k_w    = (const float*)d_in[13];
    const float* k_b    = (const float*)d_in[14];
    const float* v_w    = (const float*)d_in[15];
    const float* v_b    = (const float*)d_in[16];
    const float* o_w    = (const float*)d_in[17];
    const float* o_b    = (const float*)d_in[18];
    const float* ffn_nw = (const float*)d_in[19];
    const float* fin_w  = (const float*)d_in[20];
    const float* fin_b  = (const float*)d_in[21];
    const float* fout_w = (const float*)d_in[22];
    const float* fout_b = (const float*)d_in[23];
    const float* ss     = (const float*)d_in[24];
    const float* ps     = (const float*)d_in[25];
    const float* qss    = (const float*)d_in[26];
    float* out = (float*)d_out;

    float* base = nullptr;
    cudaGetSymbolAddress((void**)&base, g_scratch);
    float* p_ln  = base;
    float* p_lh  = base + (size_t)1 * SZ_SMALL;
    float* p_k   = base + (size_t)2 * SZ_SMALL;
    float* p_v   = base + (size_t)3 * SZ_SMALL;
    float* p_A   = base + (size_t)4 * SZ_SMALL;
    float* p_h2  = p_A  + (size_t)1 * SZ_BIG;
    float* p_u   = p_h2 + (size_t)2 * SZ_BIG;
    float* p_qh  = p_u  + (size_t)1 * SZ_BIG;
    float* p_hid = p_qh + (size_t)1 * SZ_BIG;
    uint32_t* wp = (uint32_t*)(p_hid + (size_t)1 * SZ_BIG);
    const int CC = Cc * Cc;                     // 65536
    uint32_t* w_lp   = wp;
    uint32_t* w_k    = wp + 1 * CC;
    uint32_t* w_v    = wp + 2 * CC;
    uint32_t* w_q    = wp + 3 * CC;
    uint32_t* w_o    = wp + 4 * CC;
    uint32_t* w_qout = wp + 5 * CC;
    uint32_t* w_fout = wp + 6 * CC;
    uint32_t* w_qin  = wp + 7 * CC;             // 2*CC
    uint32_t* w_fin  = wp + 9 * CC;             // 2*CC

    cudaFuncSetAttribute(gemm_mma, cudaFuncAttributeMaxDynamicSharedMemorySize, GEMM_SMEM);

    // pack weights (tiny)
    packw_kernel<<<CC / 256, 256>>>(lp_w,   w_lp,   CC);
    packw_kernel<<<CC / 256, 256>>>(k_w,    w_k,    CC);
    packw_kernel<<<CC / 256, 256>>>(v_w,    w_v,    CC);
    packw_kernel<<<CC / 256, 256>>>(q_w,    w_q,    CC);
    packw_kernel<<<CC / 256, 256>>>(o_w,    w_o,    CC);
    packw_kernel<<<CC / 256, 256>>>(qout_w, w_qout, CC);
    packw_kernel<<<CC / 256, 256>>>(fout_w, w_fout, CC);
    packw_kernel<<<2 * CC / 256, 256>>>(qin_w, w_qin, 2 * CC);
    packw_kernel<<<2 * CC / 256, 256>>>(fin_w, w_fin, 2 * CC);

    const int NTB = Tt * NBn;   // 8192
    const int NTF = Tt * NFf;   // 65536

    // latent path
    rms_kernel<<<(Bb * Tt * NBn) / 256, 256>>>(latent, lp_nw, (uint32_t*)p_ln, NBn, Bb * Tt * NBn);
    dim3 gNB(NTB / 128, 2, Bb);
    gemm_mma<<<gNB, 512, GEMM_SMEM>>>(w_lp, (const uint32_t*)p_ln, p_lh, lp_b, nullptr, nullptr, nullptr, Cc, NTB, 1, 1);
    gemm_mma<<<gNB, 512, GEMM_SMEM>>>(w_k, (const uint32_t*)p_lh, p_k, k_b, nullptr, nullptr, nullptr, Cc, NTB, 0, 0);
    gemm_mma<<<gNB, 512, GEMM_SMEM>>>(w_v, (const uint32_t*)p_lh, p_v, v_b, nullptr, nullptr, nullptr, Cc, NTB, 0, 0);

    // query path
    rms_kernel<<<(Bb * Tt * NFf) / 256, 256>>>(side, qn_w, (uint32_t*)p_A, NFf, Bb * Tt * NFf);
    dim3 gIN(NTF / 128, 4, Bb);
    gemm_mma<<<gIN, 512, GEMM_SMEM>>>(w_qin, (const uint32_t*)p_A, p_h2, qin_b, nullptr, nullptr, nullptr, 2 * Cc, NTF, 0, 0);
    swiglu_kernel<<<(Bb * Cc * Tt * NFf / 4) / 256, 256>>>(p_h2, (uint32_t*)p_u);
    dim3 gNF(NTF / 128, 2, Bb);
    gemm_mma<<<gNF, 512, GEMM_SMEM>>>(w_qout, (const uint32_t*)p_u, p_qh, qout_b, nullptr, nullptr, nullptr, Cc, NTF, 0, 1);
    gemm_mma<<<gNF, 512, GEMM_SMEM>>>(w_q, (const uint32_t*)p_qh, p_A, q_b, nullptr, nullptr, nullptr, Cc, NTF, 0, 0);

    // attention (fp32 in, packed out)
    attn_kernel<<<dim3(NFf / 128, Tt, Bb), 256>>>(p_A, p_k, p_v, eb, ss, ps, (uint32_t*)p_u);

    // output proj + packed query skip -> fp32 hid
    gemm_mma<<<gNF, 512, GEMM_SMEM>>>(w_o, (const uint32_t*)p_u, p_hid, o_b, nullptr, (const uint32_t*)p_qh, qss, Cc, NTF, 0, 0);

    // FFN
    rms_kernel<<<(Bb * Tt * NFf) / 256, 256>>>(p_hid, ffn_nw, (uint32_t*)p_A, NFf, Bb * Tt * NFf);
    gemm_mma<<<gIN, 512, GEMM_SMEM>>>(w_fin, (const uint32_t*)p_A, p_h2, fin_b, nullptr, nullptr, nullptr, 2 * Cc, NTF, 0, 0);
    swiglu_kernel<<<(Bb * Cc * Tt * NFf / 4) / 256, 256>>>(p_h2, (uint32_t*)p_u);
    gemm_mma<<<gNF, 512, GEMM_SMEM>>>(w_fout, (const uint32_t*)p_u, out, fout_b, p_hid, nullptr, nullptr, Cc, NTF, 0, 0);
}

// round 15
// speedup vs baseline: 1.1004x; 1.0441x over previous
#include <cuda_runtime.h>
#include <cuda_bf16.h>
#include <math.h>
#include <stdint.h>

#define Bb 4
#define Cc 256
#define Tt 128
#define NBn 64
#define NFf 512

#define SZ_SMALL (Bb * Cc * Tt * NBn)
#define SZ_BIG   (Bb * Cc * Tt * NFf)
#define SZ_WPACK (1 << 20)
__device__ float g_scratch[(size_t)4 * SZ_SMALL + (size_t)6 * SZ_BIG + SZ_WPACK + 4096];

__device__ __forceinline__ uint32_t smem_u32(const void* p) {
    uint32_t a;
    asm("{ .reg .u64 t; cvta.to.shared.u64 t, %1; cvt.u32.u64 %0, t; }" : "=r"(a) : "l"(p));
    return a;
}
#define SWZ128(x) ((x) ^ (((x) >> 3) & 0x70))

// pack fp32 -> (hi bf16 << 16) | lo bf16
__device__ __forceinline__ uint32_t packf(float x) {
    __nv_bfloat16 h = __float2bfloat16(x);
    float hf = __bfloat162float(h);
    __nv_bfloat16 l = __float2bfloat16(x - hf);
    return ((uint32_t)__bfloat16_as_ushort(h) << 16) | (uint32_t)__bfloat16_as_ushort(l);
}
__device__ __forceinline__ float unpackf(uint32_t u) {
    return __bfloat162float(__ushort_as_bfloat16((unsigned short)(u >> 16))) +
           __bfloat162float(__ushort_as_bfloat16((unsigned short)(u & 0xFFFFu)));
}

#define LDM_X4(r0, r1, r2, r3, a) \
    asm volatile("ldmatrix.sync.aligned.m8n8.x4.shared.b16 {%0,%1,%2,%3}, [%4];" \
        : "=r"(r0), "=r"(r1), "=r"(r2), "=r"(r3) : "r"(a))
#define MMA_BF16(c, a, b0, b1) \
    asm volatile("mma.sync.aligned.m16n8k16.row.col.f32.bf16.bf16.f32 " \
        "{%0,%1,%2,%3}, {%4,%5,%6,%7}, {%8,%9}, {%0,%1,%2,%3};" \
        : "+f"((c)[0]), "+f"((c)[1]), "+f"((c)[2]), "+f"((c)[3]) \
        : "r"((a)[0]), "r"((a)[1]), "r"((a)[2]), "r"((a)[3]), "r"(b0), "r"(b1))

// ---- weight pack kernels ----
__global__ void packw_kernel(const float* __restrict__ in, uint32_t* __restrict__ out, int n) {
    int i = blockIdx.x * blockDim.x + threadIdx.x;
    if (i < n) out[i] = packf(in[i]);
}
// interleave 2C weight rows for fused swiglu: out row mi -> in row:
//   block=mi/16, slot=mi%16, c=block*8+(slot&7); src = (slot<8) ? c : c+256
__global__ void packw_swiglu(const float* __restrict__ w, const float* __restrict__ b,
                             uint32_t* __restrict__ wo, float* __restrict__ bo) {
    int i = blockIdx.x * blockDim.x + threadIdx.x;   // over 512*256
    int mi = i >> 8, k = i & 255;
    int slot = mi & 15;
    int c = ((mi >> 4) << 3) + (slot & 7);
    int src = (slot < 8) ? c : c + 256;
    wo[mi * 256 + k] = packf(w[src * 256 + k]);
    if (k == 0) bo[mi] = b[src];
}

// ===== HMMA GEMM on pre-split packed operands =====
// Y[b,m,n] = sum_k W[m,k] X[b,k,n], K=256; W,X packed u32 (hi|lo bf16).
// 512 thr / 16 warps, tile 128x128, Kc=64, double-buffered 2x64KB smem.
// act: 0 none, 1 silu, 2 fused swiglu (interleaved rows; writes Mout/2 packed rows)
__global__ void __launch_bounds__(512) gemm_mma(
    const uint32_t* __restrict__ W, const uint32_t* __restrict__ X, void* __restrict__ Yv,
    const float* __restrict__ bias, const float* __restrict__ skipF,
    const uint32_t* __restrict__ skipP, const float* __restrict__ sscale_p,
    int Mout, int N, int act, int outMode) {
    extern __shared__ char smem[];
    const uint32_t sb = smem_u32(smem);
    const int tid = threadIdx.x, wid = tid >> 5, lane = tid & 31;
    const long bXoff = (long)blockIdx.z * 256 * N;
    const long bYoff = (long)blockIdx.z * Mout * N;
    const int n0 = blockIdx.x * 128;
    const int m0 = blockIdx.y * 128;

    const int ag = tid & 7, ar = tid >> 3;
    const int bkg = wid & 7, bnh = wid >> 3;

    uint32_t aP[16], bP[16];

    auto stage = [&](uint32_t tb) {
        #pragma unroll
        for (int it = 0; it < 2; it++) {
            const uint32_t* p = &aP[it * 8];
            uint32_t h0 = __byte_perm(p[0], p[1], 0x7632), l0 = __byte_perm(p[0], p[1], 0x5410);
            uint32_t h1 = __byte_perm(p[2], p[3], 0x7632), l1 = __byte_perm(p[2], p[3], 0x5410);
            uint32_t h2 = __byte_perm(p[4], p[5], 0x7632), l2 = __byte_perm(p[4], p[5], 0x5410);
            uint32_t h3 = __byte_perm(p[6], p[7], 0x7632), l3 = __byte_perm(p[6], p[7], 0x5410);
            uint32_t off = SWZ128((uint32_t)((ar + it * 64) * 128 + ag * 16));
            asm volatile("st.shared.v4.b32 [%0], {%1,%2,%3,%4};" :: "r"(tb + off), "r"(h0), "r"(h1), "r"(h2), "r"(h3) : "memory");
            asm volatile("st.shared.v4.b32 [%0], {%1,%2,%3,%4};" :: "r"(tb + 16384 + off), "r"(l0), "r"(l1), "r"(l2), "r"(l3) : "memory");
        }
        #pragma unroll
        for (int it = 0; it < 2; it++) {
            int n = lane + bnh * 32 + it * 64;
            const uint32_t* p = &bP[it * 8];
            uint32_t h0 = __byte_perm(p[0], p[1], 0x7632), l0 = __byte_perm(p[0], p[1], 0x5410);
            uint32_t h1 = __byte_perm(p[2], p[3], 0x7632), l1 = __byte_perm(p[2], p[3], 0x5410);
            uint32_t h2 = __byte_perm(p[4], p[5], 0x7632), l2 = __byte_perm(p[4], p[5], 0x5410);
            uint32_t h3 = __byte_perm(p[6], p[7], 0x7632), l3 = __byte_perm(p[6], p[7], 0x5410);
            uint32_t off = SWZ128((uint32_t)(n * 128 + bkg * 16));
            asm volatile("st.shared.v4.b32 [%0], {%1,%2,%3,%4};" :: "r"(tb + 32768 + off), "r"(h0), "r"(h1), "r"(h2), "r"(h3) : "memory");
            asm volatile("st.shared.v4.b32 [%0], {%1,%2,%3,%4};" :: "r"(tb + 49152 + off), "r"(l0), "r"(l1), "r"(l2), "r"(l3) : "memory");
        }
    };
    auto gload = [&](int ch) {
        #pragma unroll
        for (int it = 0; it < 2; it++) {
            const uint32_t* s = W + (long)(m0 + ar + it * 64) * 256 + ch * 64 + ag * 8;
            uint4 u0 = *(const uint4*)s, u1 = *(const uint4*)(s + 4);
            aP[it*8+0]=u0.x; aP[it*8+1]=u0.y; aP[it*8+2]=u0.z; aP[it*8+3]=u0.w;
            aP[it*8+4]=u1.x; aP[it*8+5]=u1.y; aP[it*8+6]=u1.z; aP[it*8+7]=u1.w;
        }
        #pragma unroll
        for (int it = 0; it < 2; it++) {
            int n = lane + bnh * 32 + it * 64;
            const uint32_t* s = X + bXoff + (long)(ch * 64 + bkg * 8) * N + n0 + n;
            #pragma unroll
            for (int j = 0; j < 8; j++) bP[it*8+j] = s[(long)j * N];
        }
    };

    const int wm = wid & 3, wn = wid >> 2;
    float acc[2][4][4];
    #pragma unroll
    for (int mi = 0; mi < 2; mi++)
        #pragma unroll
        for (int ni = 0; ni < 4; ni++)
            #pragma unroll
            for (int r = 0; r < 4; r++) acc[mi][ni][r] = 0.0f;

    uint32_t aRow[2], aMask[2];
    #pragma unroll
    for (int mi = 0; mi < 2; mi++) {
        uint32_t row = wm * 32 + mi * 16 + (lane & 15);
        aRow[mi] = row * 128; aMask[mi] = (aRow[mi] >> 3) & 0x70;
    }
    const uint32_t aKH = (lane >> 4) * 16;
    uint32_t bRow[2], bMask[2];
    #pragma unroll
    for (int pr = 0; pr < 2; pr++) {
        uint32_t nr = wn * 32 + pr * 16 + (lane >> 4) * 8 + (lane & 7);
        bRow[pr] = nr * 128; bMask[pr] = (bRow[pr] >> 3) & 0x70;
    }
    const uint32_t bKH = ((lane >> 3) & 1) * 16;

    gload(0);
    stage(sb);
    __syncthreads();

    for (int ch = 0; ch < 4; ch++) {
        if (ch < 3) gload(ch + 1);
        const uint32_t cb = sb + (uint32_t)(ch & 1) * 65536u;
        #pragma unroll
        for (int kk = 0; kk < 4; kk++) {
            uint32_t ah[2][4], al[2][4], bh[4][2], bl[4][2];
            const uint32_t ko = (uint32_t)(kk * 32);
            #pragma unroll
            for (int mi = 0; mi < 2; mi++) {
                uint32_t koff = ko + aKH;
                LDM_X4(ah[mi][0], ah[mi][1], ah[mi][2], ah[mi][3],
                       cb + aRow[mi] + (koff ^ aMask[mi]));
                LDM_X4(al[mi][0], al[mi][1], al[mi][2], al[mi][3],
                       cb + 16384 + aRow[mi] + (koff ^ aMask[mi]));
            }
            #pragma unroll
            for (int pr = 0; pr < 2; pr++) {
                uint32_t koff = ko + bKH;
                LDM_X4(bh[pr*2][0], bh[pr*2][1], bh[pr*2+1][0], bh[pr*2+1][1],
                       cb + 32768 + bRow[pr] + (koff ^ bMask[pr]));
                LDM_X4(bl[pr*2][0], bl[pr*2][1], bl[pr*2+1][0], bl[pr*2+1][1],
                       cb + 49152 + bRow[pr] + (koff ^ bMask[pr]));
            }
            #pragma unroll
            for (int mi = 0; mi < 2; mi++)
                #pragma unroll
                for (int ni = 0; ni < 4; ni++)
                    MMA_BF16(acc[mi][ni], ah[mi], bh[ni][0], bh[ni][1]);
            #pragma unroll
            for (int mi = 0; mi < 2; mi++)
                #pragma unroll
                for (int ni = 0; ni < 4; ni++)
                    MMA_BF16(acc[mi][ni], ah[mi], bl[ni][0], bl[ni][1]);
            #pragma unroll
            for (int mi = 0; mi < 2; mi++)
                #pragma unroll
                for (int ni = 0; ni < 4; ni++)
                    MMA_BF16(acc[mi][ni], al[mi], bh[ni][0], bh[ni][1]);
        }
        if (ch < 3) stage(sb + (uint32_t)((ch + 1) & 1) * 65536u);
        __syncthreads();
    }

    // epilogue
    const int gid = lane >> 2, tig = lane & 3;
    const float sc = sscale_p ? *sscale_p : 1.0f;
    float* Yf = (float*)Yv;
    uint32_t* Yp = (uint32_t*)Yv;
    #pragma unroll
    for (int mi = 0; mi < 2; mi++) {
        #pragma unroll
        for (int ni = 0; ni < 4; ni++) {
            int m1 = m0 + wm * 32 + mi * 16 + gid;
            int n  = n0 + wn * 32 + ni * 8 + tig * 2;
            float v0 = acc[mi][ni][0] + bias[m1];
            float v1 = acc[mi][ni][1] + bias[m1];
            float v2 = acc[mi][ni][2] + bias[m1 + 8];
            float v3 = acc[mi][ni][3] + bias[m1 + 8];
            if (act == 2) {
                // fused swiglu: rows m1 = a-channel, m1+8 = matching g-channel
                float g0 = v2 / (1.0f + expf(-v2));
                float g1 = v3 / (1.0f + expf(-v3));
                float u0 = v0 * g0, u1 = v1 * g1;
                int cch = ((m1 >> 4) << 3) + (m1 & 7);
                long o = (long)blockIdx.z * (Mout >> 1) * N + (long)cch * N + n;
                *(uint2*)&Yp[o] = make_uint2(packf(u0), packf(u1));
                continue;
            }
            if (act == 1) {
                v0 = v0 / (1.0f + expf(-v0)); v1 = v1 / (1.0f + expf(-v1));
                v2 = v2 / (1.0f + expf(-v2)); v3 = v3 / (1.0f + expf(-v3));
            }
            long o1 = bYoff + (long)m1 * N + n;
            long o2 = o1 + (long)8 * N;
            if (skipF) {
                float2 s1 = *(const float2*)&skipF[o1];
                float2 s2 = *(const float2*)&skipF[o2];
                v0 += sc * s1.x; v1 += sc * s1.y; v2 += sc * s2.x; v3 += sc * s2.y;
            } else if (skipP) {
                uint2 s1 = *(const uint2*)&skipP[o1];
                uint2 s2 = *(const uint2*)&skipP[o2];
                v0 += sc * unpackf(s1.x); v1 += sc * unpackf(s1.y);
                v2 += sc * unpackf(s2.x); v3 += sc * unpackf(s2.y);
            }
            if (outMode == 0) {
                *(float2*)&Yf[o1] = make_float2(v0, v1);
                *(float2*)&Yf[o2] = make_float2(v2, v3);
            } else {
                *(uint2*)&Yp[o1] = make_uint2(packf(v0), packf(v1));
                *(uint2*)&Yp[o2] = make_uint2(packf(v2), packf(v3));
            }
        }
    }
}

// ---------------- RMSNorm: fp32 in -> packed out ----------------
__global__ void rms_kernel(const float* __restrict__ x, const float* __restrict__ w,
                           uint32_t* __restrict__ y, int Wd, int total) {
    int idx = blockIdx.x * blockDim.x + threadIdx.x;
    if (idx >= total) return;
    int wcol = idx % Wd;
    int bt   = idx / Wd;
    int b = bt / Tt, t = bt % Tt;
    long base   = (long)b * Cc * Tt * Wd + (long)t * Wd + wcol;
    long stride = (long)Tt * Wd;
    float sum = 0.0f;
    #pragma unroll 8
    for (int c = 0; c < Cc; c++) {
        float v = x[base + (long)c * stride];
        sum += v * v;
    }
    float sc = rsqrtf(sum * (1.0f / Cc) + 1e-6f);
    #pragma unroll 8
    for (int c = 0; c < Cc; c++)
        y[base + (long)c * stride] = packf(x[base + (long)c * stride] * sc * w[c]);
}

// ---------------- fused attention: fp32 q/k/v in, packed att out -------------
__global__ void __launch_bounds__(256) attn_kernel(
    const float* __restrict__ q, const float* __restrict__ k, const float* __restrict__ v,
    const float* __restrict__ eb, const float* __restrict__ ssp, const float* __restrict__ psp,
    uint32_t* __restrict__ att) {
    __shared__ float sm[64 * 128 + 64 * 36];
    float* wst = sm;
    float* vs  = sm + 64 * 128;
    float* qs  = sm;
    float* ks  = sm + 32 * 128;

    const int f0 = blockIdx.x * 128;
    const int t  = blockIdx.y;
    const int b  = blockIdx.z;
    const int tid = threadIdx.x;
    const long qbase = (long)b * Cc * Tt * NFf + (long)t * NFf;
    const long kbase = (long)b * Cc * Tt * NBn + (long)t * NBn;
    const float ss = *ssp, ps = *psp;
    const int tx = tid & 15, ty = tid >> 4;

    float s[8][4];
    #pragma unroll
    for (int i = 0; i < 8; i++)
        #pragma unroll
        for (int j = 0; j < 4; j++) s[i][j] = 0.0f;

    for (int c0 = 0; c0 < Cc; c0 += 32) {
        {
            const int fc = (tid & 31) << 2;
            const int cr = tid >> 5;
            #pragma unroll
            for (int r = 0; r < 4; r++) {
                int cc = cr + r * 8;
                *(float4*)&qs[cc * 128 + fc] =
                    *(const float4*)&q[qbase + (long)(c0 + cc) * Tt * NFf + f0 + fc];
            }
            const int nc  = (tid & 15) << 2;
            const int cr2 = tid >> 4;
            #pragma unroll
            for (int r = 0; r < 2; r++) {
                int cc = cr2 + r * 16;
                *(float4*)&ks[cc * 64 + nc] =
                    *(const float4*)&k[kbase + (long)(c0 + cc) * Tt * NBn + nc];
            }
        }
        __syncthreads();
        #pragma unroll 8
        for (int cc = 0; cc < 32; cc++) {
            float4 a0 = *(float4*)&qs[cc * 128 + ty * 8];
            float4 a1 = *(float4*)&qs[cc * 128 + ty * 8 + 4];
            float4 b4 = *(float4*)&ks[cc * 64 + tx * 4];
            float av[8] = {a0.x, a0.y, a0.z, a0.w, a1.x, a1.y, a1.z, a1.w};
            float bv[4] = {b4.x, b4.y, b4.z, b4.w};
            #pragma unroll
            for (int i = 0; i < 8; i++)
                #pragma unroll
                for (int j = 0; j < 4; j++)
                    s[i][j] += av[i] * bv[j];
        }
        __syncthreads();
    }

    #pragma unroll
    for (int i = 0; i < 8; i++) {
        const int f = f0 + ty * 8 + i;
        float mx = -1e30f;
        #pragma unroll
        for (int j = 0; j < 4; j++) {
            s[i][j] = s[i][j] * ss + eb[(tx * 4 + j) * NFf + f] * ps;
            mx = fmaxf(mx, s[i][j]);
        }
        #pragma unroll
        for (int o = 8; o > 0; o >>= 1)
            mx = fmaxf(mx, __shfl_xor_sync(0xffffffffu, mx, o, 16));
        float sum = 0.0f;
        #pragma unroll
        for (int j = 0; j < 4; j++) { float e = expf(s[i][j] - mx); s[i][j] = e; sum += e; }
        #pragma unroll
        for (int o = 8; o > 0; o >>= 1)
            sum += __shfl_xor_sync(0xffffffffu, sum, o, 16);
        float inv = 1.0f / sum;
        #pragma unroll
        for (int j = 0; j < 4; j++) s[i][j] *= inv;
    }

    #pragma unroll
    for (int i = 0; i < 8; i++)
        #pragma unroll
        for (int j = 0; j < 4; j++)
            wst[(tx * 4 + j) * 128 + ty * 8 + i] = s[i][j];

    const int fx = tid & 15, cg = tid >> 4;
    for (int c0 = 0; c0 < Cc; c0 += 32) {
        {
            const int nc = (tid & 15) << 2;
            const int cr = tid >> 4;
            #pragma unroll
            for (int r = 0; r < 2; r++) {
                int cc = cr + r * 16;
                float4 vv4 = *(const float4*)&v[kbase + (long)(c0 + cc) * Tt * NBn + nc];
                vs[(nc + 0) * 36 + cc] = vv4.x;
                vs[(nc + 1) * 36 + cc] = vv4.y;
                vs[(nc + 2) * 36 + cc] = vv4.z;
                vs[(nc + 3) * 36 + cc] = vv4.w;
            }
        }
        __syncthreads();
        float a0[8], a1[8];
        #pragma unroll
        for (int jj = 0; jj < 8; jj++) { a0[jj] = 0.0f; a1[jj] = 0.0f; }
        #pragma unroll 16
        for (int n = 0; n < 64; n++) {
            float4 wa = *(float4*)&wst[n * 128 + fx * 8];
            float4 wb = *(float4*)&wst[n * 128 + fx * 8 + 4];
            float2 vv = *(float2*)&vs[n * 36 + cg * 2];
            float w8[8] = {wa.x, wa.y, wa.z, wa.w, wb.x, wb.y, wb.z, wb.w};
            #pragma unroll
            for (int jj = 0; jj < 8; jj++) {
                a0[jj] += vv.x * w8[jj];
                a1[jj] += vv.y * w8[jj];
            }
        }
        int c = c0 + cg * 2;
        long o0 = qbase + (long)c * Tt * NFf + f0 + fx * 8;
        long o1 = o0 + (long)Tt * NFf;
        *(uint4*)&att[o0]     = make_uint4(packf(a0[0]), packf(a0[1]), packf(a0[2]), packf(a0[3]));
        *(uint4*)&att[o0 + 4] = make_uint4(packf(a0[4]), packf(a0[5]), packf(a0[6]), packf(a0[7]));
        *(uint4*)&att[o1]     = make_uint4(packf(a1[0]), packf(a1[1]), packf(a1[2]), packf(a1[3]));
        *(uint4*)&att[o1 + 4] = make_uint4(packf(a1[4]), packf(a1[5]), packf(a1[6]), packf(a1[7]));
        __syncthreads();
    }
}

// ---------------- launch ----------------
#define GEMM_SMEM 131072
extern "C" void kernel_launch(void* const* d_in, const int* in_sizes, int n_in,
                              void* d_out, int out_size) {
    (void)in_sizes; (void)n_in; (void)out_size;
    const float* latent = (const float*)d_in[0];
    const float* side   = (const float*)d_in[1];
    const float* eb     = (const float*)d_in[2];
    const float* lp_nw  = (const float*)d_in[3];
    const float* lp_w   = (const float*)d_in[4];
    const float* lp_b   = (const float*)d_in[5];
    const float* qn_w   = (const float*)d_in[6];
    const float* qin_w  = (const float*)d_in[7];
    const float* qin_b  = (const float*)d_in[8];
    const float* qout_w = (const float*)d_in[9];
    const float* qout_b = (const float*)d_in[10];
    const float* q_w    = (const float*)d_in[11];
    const float* q_b    = (const float*)d_in[12];
    const float* k_w    = (const float*)d_in[13];
    const float* k_b    = (const float*)d_in[14];
    const float* v_w    = (const float*)d_in[15];
    const float* v_b    = (const float*)d_in[16];
    const float* o_w    = (const float*)d_in[17];
    const float* o_b    = (const float*)d_in[18];
    const float* ffn_nw = (const float*)d_in[19];
    const float* fin_w  = (const float*)d_in[20];
    const float* fin_b  = (const float*)d_in[21];
    const float* fout_w = (const float*)d_in[22];
    const float* fout_b = (const float*)d_in[23];
    const float* ss     = (const float*)d_in[24];
    const float* ps     = (const float*)d_in[25];
    const float* qss    = (const float*)d_in[26];
    float* out = (float*)d_out;

    float* base = nullptr;
    cudaGetSymbolAddress((void**)&base, g_scratch);
    float* p_ln  = base;
    float* p_lh  = base + (size_t)1 * SZ_SMALL;
    float* p_k   = base + (size_t)2 * SZ_SMALL;
    float* p_v   = base + (size_t)3 * SZ_SMALL;
    float* p_A   = base + (size_t)4 * SZ_SMALL;
    float* p_h2  = p_A  + (size_t)1 * SZ_BIG;      // (now unused; layout kept)
    float* p_u   = p_h2 + (size_t)2 * SZ_BIG;
    float* p_qh  = p_u  + (size_t)1 * SZ_BIG;
    float* p_hid = p_qh + (size_t)1 * SZ_BIG;
    uint32_t* wp = (uint32_t*)(p_hid + (size_t)1 * SZ_BIG);
    const int CC = Cc * Cc;                     // 65536
    uint32_t* w_lp   = wp;
    uint32_t* w_k    = wp + 1 * CC;
    uint32_t* w_v    = wp + 2 * CC;
    uint32_t* w_q    = wp + 3 * CC;
    uint32_t* w_o    = wp + 4 * CC;
    uint32_t* w_qout = wp + 5 * CC;
    uint32_t* w_fout = wp + 6 * CC;
    uint32_t* w_qin  = wp + 7 * CC;             // 2*CC (interleaved)
    uint32_t* w_fin  = wp + 9 * CC;             // 2*CC (interleaved)
    float* b_qin_i = (float*)(wp + 11 * CC);    // 512 floats
    float* b_fin_i = b_qin_i + 512;

    cudaFuncSetAttribute(gemm_mma, cudaFuncAttributeMaxDynamicSharedMemorySize, GEMM_SMEM);

    // pack weights
    packw_kernel<<<CC / 256, 256>>>(lp_w,   w_lp,   CC);
    packw_kernel<<<CC / 256, 256>>>(k_w,    w_k,    CC);
    packw_kernel<<<CC / 256, 256>>>(v_w,    w_v,    CC);
    packw_kernel<<<CC / 256, 256>>>(q_w,    w_q,    CC);
    packw_kernel<<<CC / 256, 256>>>(o_w,    w_o,    CC);
    packw_kernel<<<CC / 256, 256>>>(qout_w, w_qout, CC);
    packw_kernel<<<CC / 256, 256>>>(fout_w, w_fout, CC);
    packw_swiglu<<<2 * CC / 256, 256>>>(qin_w, qin_b, w_qin, b_qin_i);
    packw_swiglu<<<2 * CC / 256, 256>>>(fin_w, fin_b, w_fin, b_fin_i);

    const int NTB = Tt * NBn;   // 8192
    const int NTF = Tt * NFf;   // 65536

    // latent path
    rms_kernel<<<(Bb * Tt * NBn) / 256, 256>>>(latent, lp_nw, (uint32_t*)p_ln, NBn, Bb * Tt * NBn);
    dim3 gNB(NTB / 128, 2, Bb);
    gemm_mma<<<gNB, 512, GEMM_SMEM>>>(w_lp, (const uint32_t*)p_ln, p_lh, lp_b, nullptr, nullptr, nullptr, Cc, NTB, 1, 1);
    gemm_mma<<<gNB, 512, GEMM_SMEM>>>(w_k, (const uint32_t*)p_lh, p_k, k_b, nullptr, nullptr, nullptr, Cc, NTB, 0, 0);
    gemm_mma<<<gNB, 512, GEMM_SMEM>>>(w_v, (const uint32_t*)p_lh, p_v, v_b, nullptr, nullptr, nullptr, Cc, NTB, 0, 0);

    // query path: rms -> fused swiglu gemm -> packed u
    rms_kernel<<<(Bb * Tt * NFf) / 256, 256>>>(side, qn_w, (uint32_t*)p_A, NFf, Bb * Tt * NFf);
    dim3 gIN(NTF / 128, 4, Bb);
    gemm_mma<<<gIN, 512, GEMM_SMEM>>>(w_qin, (const uint32_t*)p_A, p_u, b_qin_i, nullptr, nullptr, nullptr, 2 * Cc, NTF, 2, 1);
    dim3 gNF(NTF / 128, 2, Bb);
    gemm_mma<<<gNF, 512, GEMM_SMEM>>>(w_qout, (const uint32_t*)p_u, p_qh, qout_b, nullptr, nullptr, nullptr, Cc, NTF, 0, 1);
    gemm_mma<<<gNF, 512, GEMM_SMEM>>>(w_q, (const uint32_t*)p_qh, p_A, q_b, nullptr, nullptr, nullptr, Cc, NTF, 0, 0);

    // attention (fp32 in, packed out)
    attn_kernel<<<dim3(NFf / 128, Tt, Bb), 256>>>(p_A, p_k, p_v, eb, ss, ps, (uint32_t*)p_u);

    // output proj + packed query skip -> fp32 hid
    gemm_mma<<<gNF, 512, GEMM_SMEM>>>(w_o, (const uint32_t*)p_u, p_hid, o_b, nullptr, (const uint32_t*)p_qh, qss, Cc, NTF, 0, 0);

    // FFN: rms -> fused swiglu gemm -> out gemm (+skip)
    rms_kernel<<<(Bb * Tt * NFf) / 256, 256>>>(p_hid, ffn_nw, (uint32_t*)p_A, NFf, Bb * Tt * NFf);
    gemm_mma<<<gIN, 512, GEMM_SMEM>>>(w_fin, (const uint32_t*)p_A, p_u, b_fin_i, nullptr, nullptr, nullptr, 2 * Cc, NTF, 2, 1);
    gemm_mma<<<gNF, 512, GEMM_SMEM>>>(w_fout, (const uint32_t*)p_u, out, fout_b, p_hid, nullptr, nullptr, Cc, NTF, 0, 0);
}